// round 16
// baseline (speedup 1.0000x reference)
#include <cuda_runtime.h>
#include <cuda_fp16.h>
#include <cstdint>

#define BB 2048   // batch
#define NN 512    // codebook
#define KD 8192   // C*T
#define NC_MAX 32
#define CAND_T 4.0f
#define KSPL 4
#define KPART (KD / KSPL)        // 2048

// ---------------- device scratch (no allocations allowed) -------------------
__device__ __half g_yh[(size_t)BB * KD];        // fp16 y
__device__ __half g_mh[(size_t)NN * KD];        // fp16 m
__device__ unsigned int g_parth[KSPL][BB][NN / 2];  // packed f16x2 partial dots (8 MB)
__device__ float g_mmq[NN][4];                  // per-quarter sumsq of m rows
__device__ int   g_assign[BB];
__device__ int   g_cnt[NN];
__device__ int   g_items2[(size_t)NN * BB];
__device__ int   g_nwork;
__device__ int   g_work[BB];
__device__ int   g_ncand[BB];                   // 0 => all 512
__device__ int   g_cand[BB][NC_MAX];
__device__ unsigned long long g_rkey[BB];       // packed (score, idx) min-combine

// ---------------- PTX helpers (sm_80-level ISA only) ------------------------
__device__ __forceinline__ uint32_t smem_u32(const void* p) {
    uint32_t a;
    asm("{ .reg .u64 t; cvta.to.shared.u64 t, %1; cvt.u32.u64 %0, t; }" : "=r"(a) : "l"(p));
    return a;
}
__device__ __forceinline__ void cp_async16(uint32_t dst, const void* src) {
    asm volatile("cp.async.cg.shared.global [%0], [%1], 16;" :: "r"(dst), "l"(src));
}
__device__ __forceinline__ void ldm_x4(uint32_t* r, uint32_t addr) {
    asm volatile("ldmatrix.sync.aligned.m8n8.x4.shared.b16 {%0,%1,%2,%3}, [%4];"
                 : "=r"(r[0]), "=r"(r[1]), "=r"(r[2]), "=r"(r[3]) : "r"(addr));
}
// f16-accumulator HMMA
__device__ __forceinline__ void mma_f16a(uint32_t* d, const uint32_t* a, const uint32_t* b) {
    asm volatile(
        "mma.sync.aligned.m16n8k16.row.col.f16.f16.f16.f16 "
        "{%0,%1}, {%2,%3,%4,%5}, {%6,%7}, {%0,%1};"
        : "+r"(d[0]), "+r"(d[1])
        : "r"(a[0]), "r"(a[1]), "r"(a[2]), "r"(a[3]), "r"(b[0]), "r"(b[1]));
}

// ---------------- K0: fp32 -> fp16, fused m-row sumsq partials --------------
__global__ __launch_bounds__(256) void k_quant(const float* __restrict__ y,
                                               const float* __restrict__ m) {
    if (blockIdx.x == 0 && threadIdx.x == 0) g_nwork = 0;
    const size_t YC = (size_t)BB * KD / 8;
    size_t gid = (size_t)blockIdx.x * 256 + threadIdx.x;
    const bool is_m = (gid >= YC);
    const float* src = is_m ? m : y;
    __half* dst      = is_m ? g_mh : g_yh;
    size_t e         = (is_m ? (gid - YC) : gid) * 8;

    float4 v0 = *(const float4*)(src + e);
    float4 v1 = *(const float4*)(src + e + 4);
    float f[8] = {v0.x, v0.y, v0.z, v0.w, v1.x, v1.y, v1.z, v1.w};
    __half h[8];
#pragma unroll
    for (int i = 0; i < 8; i++) h[i] = __float2half_rn(f[i]);
    *(uint4*)(dst + e) = *(uint4*)h;

    if (is_m) {
        float s = 0.f;
#pragma unroll
        for (int i = 0; i < 8; i++) s += f[i] * f[i];
        __shared__ float sh[256];
        sh[threadIdx.x] = s;
        __syncthreads();
        for (int st = 128; st > 0; st >>= 1) {
            if (threadIdx.x < st) sh[threadIdx.x] += sh[threadIdx.x + st];
            __syncthreads();
        }
        if (threadIdx.x == 0) {
            size_t eb = (size_t)(blockIdx.x - (int)(YC / 256)) * 2048;
            int row = (int)(eb / KD);
            int qtr = (int)((eb % KD) / 2048);
            g_mmq[row][qtr] = sh[0];
        }
    }
}

// ---------------- K2: fp16 HMMA dot GEMM, BM=128 BN=128 BK=64, KSPL=4 -------
// 256 threads = 8 warps (4M x 2N), warp tile 32(M) x 64(N).
#define SROW 144
#define A_MAT (128 * SROW)        // 18432
#define B_MAT (128 * SROW)        // 18432
#define STG   (A_MAT + B_MAT)     // 36864
#define DEPTH 2
#define SM_TOTAL (DEPTH * STG)    // 73728
#define NSTAGES (KPART / 64)      // 32

__device__ __forceinline__ void load_stage(uint32_t sb, int buf, int b0, int n0, int k0,
                                           int tid) {
    uint32_t stA = sb + buf * STG;
    uint32_t stB = stA + A_MAT;
#pragma unroll
    for (int t = 0; t < 4; t++) {                 // A: 128 rows x 8 x 16B
        int idx = t * 256 + tid;
        int row = idx >> 3, ch = idx & 7;
        const void* src = g_yh + (size_t)(b0 + row) * KD + k0 + ch * 8;
        cp_async16(stA + row * SROW + ch * 16, src);
    }
#pragma unroll
    for (int t = 0; t < 4; t++) {                 // B: 128 rows x 8 x 16B
        int idx = t * 256 + tid;
        int row = idx >> 3, ch = idx & 7;
        const void* src = g_mh + (size_t)(n0 + row) * KD + k0 + ch * 8;
        cp_async16(stB + row * SROW + ch * 16, src);
    }
    asm volatile("cp.async.commit_group;");
}

__global__ __launch_bounds__(256, 3) void k_gemm() {
    extern __shared__ char smem[];
    const uint32_t sb = smem_u32(smem);
    const int tid = threadIdx.x;
    const int lane = tid & 31;
    const int wid = tid >> 5;
    const int wm = wid >> 1;          // 0..3 -> M offset wm*32
    const int wn = wid & 1;           // 0..1 -> N offset wn*64
    const int b0 = blockIdx.y * 128;
    const int n0 = blockIdx.x * 128;
    const int ks = blockIdx.z;
    const int kbase = ks * KPART;

    uint32_t acc[2][8][2];            // packed f16x2 accumulators
#pragma unroll
    for (int i = 0; i < 2; i++)
#pragma unroll
        for (int j = 0; j < 8; j++) { acc[i][j][0] = 0u; acc[i][j][1] = 0u; }

    load_stage(sb, 0, b0, n0, kbase, tid);

    for (int s = 0; s < NSTAGES; s++) {
        if (s + 1 < NSTAGES) {
            load_stage(sb, (s + 1) & 1, b0, n0, kbase + (s + 1) * 64, tid);
            asm volatile("cp.async.wait_group 1;" ::: "memory");
        } else {
            asm volatile("cp.async.wait_group 0;" ::: "memory");
        }
        __syncthreads();

        uint32_t stA = sb + (s & 1) * STG;
        uint32_t stB = stA + A_MAT;

#pragma unroll
        for (int kstep = 0; kstep < 4; kstep++) {
            uint32_t ah[2][4];
#pragma unroll
            for (int mt = 0; mt < 2; mt++) {
                int row = wm * 32 + mt * 16 + (lane & 15);
                int ch = kstep * 2 + (lane >> 4);
                ldm_x4(ah[mt], stA + row * SROW + ch * 16);
            }
            uint32_t bh[8][2];
#pragma unroll
            for (int p = 0; p < 4; p++) {
                int row = wn * 64 + p * 16 + (lane & 7) + (lane >> 4) * 8;
                int ch = kstep * 2 + ((lane >> 3) & 1);
                uint32_t r4[4];
                ldm_x4(r4, stB + row * SROW + ch * 16);
                bh[p * 2 + 0][0] = r4[0]; bh[p * 2 + 0][1] = r4[1];
                bh[p * 2 + 1][0] = r4[2]; bh[p * 2 + 1][1] = r4[3];
            }
#pragma unroll
            for (int mt = 0; mt < 2; mt++)
#pragma unroll
                for (int nt = 0; nt < 8; nt++)
                    mma_f16a(acc[mt][nt], ah[mt], bh[nt]);
        }
        __syncthreads();
    }

    // epilogue: store packed f16x2 partials (bit-exact)
#pragma unroll
    for (int mt = 0; mt < 2; mt++) {
        int row0 = b0 + wm * 32 + mt * 16 + (lane >> 2);
        int row1 = row0 + 8;
#pragma unroll
        for (int nt = 0; nt < 8; nt++) {
            int colp = (n0 + wn * 64 + nt * 8 + (lane & 3) * 2) >> 1;
            g_parth[ks][row0][colp] = acc[mt][nt][0];
            g_parth[ks][row1][colp] = acc[mt][nt][1];
        }
    }
}

// ---------------- K3: combine partials, argmin + candidate collection -------
__global__ __launch_bounds__(128) void k_argmin_cand(float* __restrict__ out_assign) {
    int b = blockIdx.x;
    int tid = threadIdx.x;
    __shared__ float srow[NN];
    for (int i = tid; i < NN / 2; i += 128) {
        __half2 u0 = *(__half2*)&g_parth[0][b][i];
        __half2 u1 = *(__half2*)&g_parth[1][b][i];
        __half2 u2 = *(__half2*)&g_parth[2][b][i];
        __half2 u3 = *(__half2*)&g_parth[3][b][i];
        float d0 = (__low2float(u0) + __low2float(u1)) + (__low2float(u2) + __low2float(u3));
        float d1 = (__high2float(u0) + __high2float(u1)) + (__high2float(u2) + __high2float(u3));
        float4 mA = *(float4*)&g_mmq[2 * i][0];
        float4 mB = *(float4*)&g_mmq[2 * i + 1][0];
        srow[2 * i]     = ((mA.x + mA.y) + (mA.z + mA.w)) - 2.0f * d0;
        srow[2 * i + 1] = ((mB.x + mB.y) + (mB.z + mB.w)) - 2.0f * d1;
    }
    __syncthreads();

    float best = 3.4e38f;
    int   bi = 0;
    for (int n = tid; n < NN; n += 128) {
        float v = srow[n];
        if (v < best) { best = v; bi = n; }
    }
    __shared__ float sv[128];
    __shared__ int   si[128];
    sv[tid] = best;
    si[tid] = bi;
    __syncthreads();
    for (int st = 64; st > 0; st >>= 1) {
        if (tid < st) {
            float v2 = sv[tid + st];
            int   i2 = si[tid + st];
            if (v2 < sv[tid] || (v2 == sv[tid] && i2 < si[tid])) {
                sv[tid] = v2;
                si[tid] = i2;
            }
        }
        __syncthreads();
    }
    __shared__ int scnt;
    __shared__ int scand[NC_MAX];
    if (tid == 0) scnt = 0;
    __syncthreads();
    float thr = sv[0] + CAND_T;
    for (int n = tid; n < NN; n += 128) {
        if (srow[n] <= thr) {
            int pos = atomicAdd(&scnt, 1);
            if (pos < NC_MAX) scand[pos] = n;
        }
    }
    __syncthreads();
    if (tid == 0) {
        int minidx = si[0];
        g_assign[b]   = minidx;
        out_assign[b] = (float)minidx;
        if (scnt > 1) {
            int wi = atomicAdd(&g_nwork, 1);
            g_work[wi] = b;
            g_rkey[b] = 0xFFFFFFFFFFFFFFFFull;
            if (scnt <= NC_MAX) {
                g_ncand[b] = scnt;
                for (int c = 0; c < scnt; c++) g_cand[b][c] = scand[c];
            } else {
                g_ncand[b] = 0;            // sentinel: rescore all 512
            }
        }
    }
}

// ---------------- K3b: fp32 rescore — one BLOCK per (work, candidate) -------
// grid (BB, NC_MAX). All candidates of all rows run fully in parallel; each
// block computes one dot with all 256 threads (32 elems = 8 float4/stream
// per thread), then fixed-order deterministic reduce + monotone-key atomicMin.
__global__ __launch_bounds__(256) void k_rescore(const float* __restrict__ y,
                                                 const float* __restrict__ m) {
    int w = blockIdx.x;
    if (w >= g_nwork) return;
    int b  = g_work[w];
    int nc = g_ncand[b];
    int total = (nc == 0) ? NN : nc;
    int c0 = blockIdx.y;
    if (c0 >= total) return;
    int tid  = threadIdx.x;
    int lane = tid & 31;
    int warp = tid >> 5;
    const float* yrow = y + (size_t)b * KD;
    __shared__ float ws[8];

    for (int c = c0; c < total; c += NC_MAX) {     // loops >1 only for sentinel
        int n = (nc == 0) ? c : g_cand[b][c];
        const float* mrow = m + (size_t)n * KD;
        // per-thread: 8 float4 per stream at offsets tid*4 + i*1024
        float s0 = 0.f, s1 = 0.f, s2 = 0.f, s3 = 0.f;
#pragma unroll
        for (int i = 0; i < 8; i++) {
            float4 mk = *(const float4*)(mrow + tid * 4 + i * 1024);
            float4 yk = *(const float4*)(yrow + tid * 4 + i * 1024);
            s0 += mk.x * (mk.x - 2.0f * yk.x);
            s1 += mk.y * (mk.y - 2.0f * yk.y);
            s2 += mk.z * (mk.z - 2.0f * yk.z);
            s3 += mk.w * (mk.w - 2.0f * yk.w);
        }
        float s = (s0 + s1) + (s2 + s3);
#pragma unroll
        for (int off = 16; off > 0; off >>= 1)
            s += __shfl_down_sync(0xffffffffu, s, off);
        if (lane == 0) ws[warp] = s;
        __syncthreads();
        if (tid == 0) {
            float t = ((ws[0] + ws[1]) + (ws[2] + ws[3])) +
                      ((ws[4] + ws[5]) + (ws[6] + ws[7]));
            unsigned int u = __float_as_uint(t);
            u = (u & 0x80000000u) ? ~u : (u ^ 0x80000000u);   // monotone order map
            unsigned long long key = ((unsigned long long)u << 32) | (unsigned long long)n;
            atomicMin(&g_rkey[b], key);
        }
        __syncthreads();
    }
}

// ---------------- K3c: finalize rescored assignments ------------------------
__global__ __launch_bounds__(256) void k_rescore_fin(float* __restrict__ out_assign) {
    int i = blockIdx.x * 256 + threadIdx.x;
    if (i >= g_nwork) return;
    int b = g_work[i];
    int n = (int)(g_rkey[b] & 0xFFFFFFFFull);
    g_assign[b]   = n;
    out_assign[b] = (float)n;
}

// ---------------- K4: stable per-centroid compaction (1 warp / centroid) ----
__global__ __launch_bounds__(32) void k_group(const float* __restrict__ p_in,
                                              float* __restrict__ p_out) {
    int z = blockIdx.x;
    int lane = threadIdx.x;
    int pos = 0;
    for (int c = 0; c < BB; c += 32) {
        int a = g_assign[c + lane];
        unsigned msk = __ballot_sync(0xffffffffu, a == z);
        if (a == z)
            g_items2[(size_t)z * BB + pos + __popc(msk & ((1u << lane) - 1))] = c + lane;
        pos += __popc(msk);
    }
    if (lane == 0) {
        g_cnt[z] = pos;
        p_out[z] = p_in[z] + (float)pos;
    }
}

// ---------------- K5: EMA chains, KD split 8-way + register prefetch --------
#define GCH 8
#define CHUNK (KD / GCH)

__global__ __launch_bounds__(256) void k_update(const float* __restrict__ Y,
                                                const float* __restrict__ Min,
                                                const float* __restrict__ SDin,
                                                float* __restrict__ out_m,
                                                float* __restrict__ out_sd) {
    int z   = blockIdx.x;
    int g   = blockIdx.y;
    int tid = threadIdx.x;
    const size_t base = (size_t)z * KD + (size_t)g * CHUNK;

    float4 mv = ((const float4*)(Min  + base))[tid];
    float4 sv = ((const float4*)(SDin + base))[tid];
    int cnt = g_cnt[z];
    const int* items = g_items2 + (size_t)z * BB;

    float4 ycur, ynxt;
    if (cnt > 0)
        ycur = ((const float4*)(Y + (size_t)items[0] * KD + (size_t)g * CHUNK))[tid];
    for (int j = 0; j < cnt; j++) {
        if (j + 1 < cnt)
            ynxt = ((const float4*)(Y + (size_t)items[j + 1] * KD + (size_t)g * CHUNK))[tid];
        float4 yv = ycur;
        float d;
        mv.x = mv.x * 0.001f + yv.x * 0.999f;
        d = mv.x - yv.x; sv.x = d * d * 0.001f + sv.x * 0.999f;
        mv.y = mv.y * 0.001f + yv.y * 0.999f;
        d = mv.y - yv.y; sv.y = d * d * 0.001f + sv.y * 0.999f;
        mv.z = mv.z * 0.001f + yv.z * 0.999f;
        d = mv.z - yv.z; sv.z = d * d * 0.001f + sv.z * 0.999f;
        mv.w = mv.w * 0.001f + yv.w * 0.999f;
        d = mv.w - yv.w; sv.w = d * d * 0.001f + sv.w * 0.999f;
        ycur = ynxt;
    }
    ((float4*)(out_m  + base))[tid] = mv;
    ((float4*)(out_sd + base))[tid] = sv;
}

// ---------------- launch ----------------------------------------------------
extern "C" void kernel_launch(void* const* d_in, const int* in_sizes, int n_in,
                              void* d_out, int out_size) {
    const float* y  = (const float*)d_in[0];
    const float* m  = (const float*)d_in[1];
    const float* sd = (const float*)d_in[2];
    const float* p  = (const float*)d_in[3];

    float* out      = (float*)d_out;
    float* out_m    = out;
    float* out_sd   = out + (size_t)NN * KD;
    float* out_p    = out + 2 * (size_t)NN * KD;
    float* out_asgn = out_p + NN;

    cudaFuncSetAttribute(k_gemm, cudaFuncAttributeMaxDynamicSharedMemorySize, SM_TOTAL);

    const int conv_blocks = (int)(((size_t)BB * KD + (size_t)NN * KD) / 8 / 256);
    k_quant<<<conv_blocks, 256>>>(y, m);
    dim3 grid(NN / 128, BB / 128, KSPL);
    k_gemm<<<grid, 256, SM_TOTAL>>>();
    k_argmin_cand<<<BB, 128>>>(out_asgn);
    dim3 rgrid(BB, NC_MAX);
    k_rescore<<<rgrid, 256>>>(y, m);
    k_rescore_fin<<<BB / 256, 256>>>(out_asgn);
    k_group<<<NN, 32>>>(p, out_p);
    dim3 ugrid(NN, GCH);
    k_update<<<ugrid, 256>>>(y, m, sd, out_m, out_sd);
}

// round 17
// speedup vs baseline: 1.5457x; 1.5457x over previous
#include <cuda_runtime.h>
#include <cuda_fp16.h>
#include <cstdint>

#define BB 2048   // batch
#define NN 512    // codebook
#define KD 8192   // C*T
#define NC_MAX 32
#define CAND_T 4.0f
#define KSPL 4
#define KPART (KD / KSPL)        // 2048

// ---------------- device scratch (no allocations allowed) -------------------
__device__ __half g_yh[(size_t)BB * KD];        // fp16 y
__device__ __half g_mh[(size_t)NN * KD];        // fp16 m
__device__ unsigned int g_parth[KSPL][BB][NN / 2];  // packed f16x2 partial dots (8 MB)
__device__ float g_mmq[NN][4];                  // per-quarter sumsq of m rows
__device__ int   g_assign[BB];
__device__ int   g_cnt[NN];
__device__ int   g_items2[(size_t)NN * BB];

// ---------------- PTX helpers (sm_80-level ISA only) ------------------------
__device__ __forceinline__ uint32_t smem_u32(const void* p) {
    uint32_t a;
    asm("{ .reg .u64 t; cvta.to.shared.u64 t, %1; cvt.u32.u64 %0, t; }" : "=r"(a) : "l"(p));
    return a;
}
__device__ __forceinline__ void cp_async16(uint32_t dst, const void* src) {
    asm volatile("cp.async.cg.shared.global [%0], [%1], 16;" :: "r"(dst), "l"(src));
}
__device__ __forceinline__ void ldm_x4(uint32_t* r, uint32_t addr) {
    asm volatile("ldmatrix.sync.aligned.m8n8.x4.shared.b16 {%0,%1,%2,%3}, [%4];"
                 : "=r"(r[0]), "=r"(r[1]), "=r"(r[2]), "=r"(r[3]) : "r"(addr));
}
// f16-accumulator HMMA
__device__ __forceinline__ void mma_f16a(uint32_t* d, const uint32_t* a, const uint32_t* b) {
    asm volatile(
        "mma.sync.aligned.m16n8k16.row.col.f16.f16.f16.f16 "
        "{%0,%1}, {%2,%3,%4,%5}, {%6,%7}, {%0,%1};"
        : "+r"(d[0]), "+r"(d[1])
        : "r"(a[0]), "r"(a[1]), "r"(a[2]), "r"(a[3]), "r"(b[0]), "r"(b[1]));
}

// ---------------- K0: fp32 -> fp16, fused m-row sumsq partials --------------
__global__ __launch_bounds__(256) void k_quant(const float* __restrict__ y,
                                               const float* __restrict__ m) {
    const size_t YC = (size_t)BB * KD / 8;
    size_t gid = (size_t)blockIdx.x * 256 + threadIdx.x;
    const bool is_m = (gid >= YC);
    const float* src = is_m ? m : y;
    __half* dst      = is_m ? g_mh : g_yh;
    size_t e         = (is_m ? (gid - YC) : gid) * 8;

    float4 v0 = *(const float4*)(src + e);
    float4 v1 = *(const float4*)(src + e + 4);
    float f[8] = {v0.x, v0.y, v0.z, v0.w, v1.x, v1.y, v1.z, v1.w};
    __half h[8];
#pragma unroll
    for (int i = 0; i < 8; i++) h[i] = __float2half_rn(f[i]);
    *(uint4*)(dst + e) = *(uint4*)h;

    if (is_m) {
        float s = 0.f;
#pragma unroll
        for (int i = 0; i < 8; i++) s += f[i] * f[i];
        __shared__ float sh[256];
        sh[threadIdx.x] = s;
        __syncthreads();
        for (int st = 128; st > 0; st >>= 1) {
            if (threadIdx.x < st) sh[threadIdx.x] += sh[threadIdx.x + st];
            __syncthreads();
        }
        if (threadIdx.x == 0) {
            size_t eb = (size_t)(blockIdx.x - (int)(YC / 256)) * 2048;
            int row = (int)(eb / KD);
            int qtr = (int)((eb % KD) / 2048);
            g_mmq[row][qtr] = sh[0];
        }
    }
}

// ---------------- K2: fp16 HMMA dot GEMM, BM=128 BN=128 BK=64, KSPL=4 -------
#define SROW 144
#define A_MAT (128 * SROW)        // 18432
#define B_MAT (128 * SROW)        // 18432
#define STG   (A_MAT + B_MAT)     // 36864
#define DEPTH 2
#define SM_TOTAL (DEPTH * STG)    // 73728
#define NSTAGES (KPART / 64)      // 32

__device__ __forceinline__ void load_stage(uint32_t sb, int buf, int b0, int n0, int k0,
                                           int tid) {
    uint32_t stA = sb + buf * STG;
    uint32_t stB = stA + A_MAT;
#pragma unroll
    for (int t = 0; t < 4; t++) {                 // A: 128 rows x 8 x 16B
        int idx = t * 256 + tid;
        int row = idx >> 3, ch = idx & 7;
        const void* src = g_yh + (size_t)(b0 + row) * KD + k0 + ch * 8;
        cp_async16(stA + row * SROW + ch * 16, src);
    }
#pragma unroll
    for (int t = 0; t < 4; t++) {                 // B: 128 rows x 8 x 16B
        int idx = t * 256 + tid;
        int row = idx >> 3, ch = idx & 7;
        const void* src = g_mh + (size_t)(n0 + row) * KD + k0 + ch * 8;
        cp_async16(stB + row * SROW + ch * 16, src);
    }
    asm volatile("cp.async.commit_group;");
}

__global__ __launch_bounds__(256, 3) void k_gemm() {
    extern __shared__ char smem[];
    const uint32_t sb = smem_u32(smem);
    const int tid = threadIdx.x;
    const int lane = tid & 31;
    const int wid = tid >> 5;
    const int wm = wid >> 1;          // 0..3 -> M offset wm*32
    const int wn = wid & 1;           // 0..1 -> N offset wn*64
    const int b0 = blockIdx.y * 128;
    const int n0 = blockIdx.x * 128;
    const int ks = blockIdx.z;
    const int kbase = ks * KPART;

    uint32_t acc[2][8][2];            // packed f16x2 accumulators
#pragma unroll
    for (int i = 0; i < 2; i++)
#pragma unroll
        for (int j = 0; j < 8; j++) { acc[i][j][0] = 0u; acc[i][j][1] = 0u; }

    load_stage(sb, 0, b0, n0, kbase, tid);

    for (int s = 0; s < NSTAGES; s++) {
        if (s + 1 < NSTAGES) {
            load_stage(sb, (s + 1) & 1, b0, n0, kbase + (s + 1) * 64, tid);
            asm volatile("cp.async.wait_group 1;" ::: "memory");
        } else {
            asm volatile("cp.async.wait_group 0;" ::: "memory");
        }
        __syncthreads();

        uint32_t stA = sb + (s & 1) * STG;
        uint32_t stB = stA + A_MAT;

#pragma unroll
        for (int kstep = 0; kstep < 4; kstep++) {
            uint32_t ah[2][4];
#pragma unroll
            for (int mt = 0; mt < 2; mt++) {
                int row = wm * 32 + mt * 16 + (lane & 15);
                int ch = kstep * 2 + (lane >> 4);
                ldm_x4(ah[mt], stA + row * SROW + ch * 16);
            }
            uint32_t bh[8][2];
#pragma unroll
            for (int p = 0; p < 4; p++) {
                int row = wn * 64 + p * 16 + (lane & 7) + (lane >> 4) * 8;
                int ch = kstep * 2 + ((lane >> 3) & 1);
                uint32_t r4[4];
                ldm_x4(r4, stB + row * SROW + ch * 16);
                bh[p * 2 + 0][0] = r4[0]; bh[p * 2 + 0][1] = r4[1];
                bh[p * 2 + 1][0] = r4[2]; bh[p * 2 + 1][1] = r4[3];
            }
#pragma unroll
            for (int mt = 0; mt < 2; mt++)
#pragma unroll
                for (int nt = 0; nt < 8; nt++)
                    mma_f16a(acc[mt][nt], ah[mt], bh[nt]);
        }
        __syncthreads();
    }

    // epilogue: store packed f16x2 partials (bit-exact)
#pragma unroll
    for (int mt = 0; mt < 2; mt++) {
        int row0 = b0 + wm * 32 + mt * 16 + (lane >> 2);
        int row1 = row0 + 8;
#pragma unroll
        for (int nt = 0; nt < 8; nt++) {
            int colp = (n0 + wn * 64 + nt * 8 + (lane & 3) * 2) >> 1;
            g_parth[ks][row0][colp] = acc[mt][nt][0];
            g_parth[ks][row1][colp] = acc[mt][nt][1];
        }
    }
}

// ---------------- K3: argmin + fused exact fp32 rescore of near-ties --------
__global__ __launch_bounds__(128) void k_argmin_rescore(const float* __restrict__ y,
                                                        const float* __restrict__ m,
                                                        float* __restrict__ out_assign) {
    int b = blockIdx.x;
    int tid = threadIdx.x;
    int lane = tid & 31;
    int warp = tid >> 5;
    __shared__ float srow[NN];
    for (int i = tid; i < NN / 2; i += 128) {
        __half2 u0 = *(__half2*)&g_parth[0][b][i];
        __half2 u1 = *(__half2*)&g_parth[1][b][i];
        __half2 u2 = *(__half2*)&g_parth[2][b][i];
        __half2 u3 = *(__half2*)&g_parth[3][b][i];
        float d0 = (__low2float(u0) + __low2float(u1)) + (__low2float(u2) + __low2float(u3));
        float d1 = (__high2float(u0) + __high2float(u1)) + (__high2float(u2) + __high2float(u3));
        float4 mA = *(float4*)&g_mmq[2 * i][0];
        float4 mB = *(float4*)&g_mmq[2 * i + 1][0];
        srow[2 * i]     = ((mA.x + mA.y) + (mA.z + mA.w)) - 2.0f * d0;
        srow[2 * i + 1] = ((mB.x + mB.y) + (mB.z + mB.w)) - 2.0f * d1;
    }
    __syncthreads();

    float best = 3.4e38f;
    int   bi = 0;
    for (int n = tid; n < NN; n += 128) {
        float v = srow[n];
        if (v < best) { best = v; bi = n; }
    }
    __shared__ float sv[128];
    __shared__ int   si[128];
    sv[tid] = best;
    si[tid] = bi;
    __syncthreads();
    for (int st = 64; st > 0; st >>= 1) {
        if (tid < st) {
            float v2 = sv[tid + st];
            int   i2 = si[tid + st];
            if (v2 < sv[tid] || (v2 == sv[tid] && i2 < si[tid])) {
                sv[tid] = v2;
                si[tid] = i2;
            }
        }
        __syncthreads();
    }
    __shared__ int scnt;
    __shared__ int scand[NC_MAX];
    if (tid == 0) scnt = 0;
    __syncthreads();
    float thr = sv[0] + CAND_T;
    for (int n = tid; n < NN; n += 128) {
        if (srow[n] <= thr) {
            int pos = atomicAdd(&scnt, 1);
            if (pos < NC_MAX) scand[pos] = n;
        }
    }
    __syncthreads();

    int cnt = scnt;
    if (cnt <= 1) {
        if (tid == 0) {
            g_assign[b]   = si[0];
            out_assign[b] = (float)si[0];
        }
        return;
    }

    // --- exact fp32 rescore of candidates, in-block, deterministic ---
    int total = (cnt <= NC_MAX) ? cnt : NN;        // sentinel: all 512
    const float* yrow = y + (size_t)b * KD;
    __shared__ float ws[4];
    __shared__ float bestv_s;
    __shared__ int   besti_s;
    if (tid == 0) { bestv_s = 3.4e38f; besti_s = 0x7fffffff; }
    __syncthreads();

    for (int c = 0; c < total; c++) {
        int n = (cnt <= NC_MAX) ? scand[c] : c;
        const float* mrow = m + (size_t)n * KD;
        float s0 = 0.f, s1 = 0.f, s2 = 0.f, s3 = 0.f;
#pragma unroll
        for (int i = 0; i < 16; i++) {             // 128 thr x 4 floats x 16 = 8192
            float4 mk = *(const float4*)(mrow + tid * 4 + i * 512);
            float4 yk = *(const float4*)(yrow + tid * 4 + i * 512);
            s0 += mk.x * (mk.x - 2.0f * yk.x);
            s1 += mk.y * (mk.y - 2.0f * yk.y);
            s2 += mk.z * (mk.z - 2.0f * yk.z);
            s3 += mk.w * (mk.w - 2.0f * yk.w);
        }
        float s = (s0 + s1) + (s2 + s3);
#pragma unroll
        for (int off = 16; off > 0; off >>= 1)
            s += __shfl_down_sync(0xffffffffu, s, off);
        if (lane == 0) ws[warp] = s;
        __syncthreads();
        if (tid == 0) {
            float t = (ws[0] + ws[1]) + (ws[2] + ws[3]);
            if (t < bestv_s || (t == bestv_s && n < besti_s)) { bestv_s = t; besti_s = n; }
        }
        __syncthreads();
    }
    if (tid == 0) {
        g_assign[b]   = besti_s;
        out_assign[b] = (float)besti_s;
    }
}

// ---------------- K4: stable per-centroid compaction (1 warp / centroid) ----
__global__ __launch_bounds__(32) void k_group(const float* __restrict__ p_in,
                                              float* __restrict__ p_out) {
    int z = blockIdx.x;
    int lane = threadIdx.x;
    int pos = 0;
    for (int c = 0; c < BB; c += 32) {
        int a = g_assign[c + lane];
        unsigned msk = __ballot_sync(0xffffffffu, a == z);
        if (a == z)
            g_items2[(size_t)z * BB + pos + __popc(msk & ((1u << lane) - 1))] = c + lane;
        pos += __popc(msk);
    }
    if (lane == 0) {
        g_cnt[z] = pos;
        p_out[z] = p_in[z] + (float)pos;
    }
}

// ---------------- K5: EMA chains, KD split 8-way + register prefetch --------
#define GCH 8
#define CHUNK (KD / GCH)

__global__ __launch_bounds__(256) void k_update(const float* __restrict__ Y,
                                                const float* __restrict__ Min,
                                                const float* __restrict__ SDin,
                                                float* __restrict__ out_m,
                                                float* __restrict__ out_sd) {
    int z   = blockIdx.x;
    int g   = blockIdx.y;
    int tid = threadIdx.x;
    const size_t base = (size_t)z * KD + (size_t)g * CHUNK;

    float4 mv = ((const float4*)(Min  + base))[tid];
    float4 sv = ((const float4*)(SDin + base))[tid];
    int cnt = g_cnt[z];
    const int* items = g_items2 + (size_t)z * BB;

    float4 ycur, ynxt;
    if (cnt > 0)
        ycur = ((const float4*)(Y + (size_t)items[0] * KD + (size_t)g * CHUNK))[tid];
    for (int j = 0; j < cnt; j++) {
        if (j + 1 < cnt)
            ynxt = ((const float4*)(Y + (size_t)items[j + 1] * KD + (size_t)g * CHUNK))[tid];
        float4 yv = ycur;
        float d;
        mv.x = mv.x * 0.001f + yv.x * 0.999f;
        d = mv.x - yv.x; sv.x = d * d * 0.001f + sv.x * 0.999f;
        mv.y = mv.y * 0.001f + yv.y * 0.999f;
        d = mv.y - yv.y; sv.y = d * d * 0.001f + sv.y * 0.999f;
        mv.z = mv.z * 0.001f + yv.z * 0.999f;
        d = mv.z - yv.z; sv.z = d * d * 0.001f + sv.z * 0.999f;
        mv.w = mv.w * 0.001f + yv.w * 0.999f;
        d = mv.w - yv.w; sv.w = d * d * 0.001f + sv.w * 0.999f;
        ycur = ynxt;
    }
    ((float4*)(out_m  + base))[tid] = mv;
    ((float4*)(out_sd + base))[tid] = sv;
}

// ---------------- launch ----------------------------------------------------
extern "C" void kernel_launch(void* const* d_in, const int* in_sizes, int n_in,
                              void* d_out, int out_size) {
    const float* y  = (const float*)d_in[0];
    const float* m  = (const float*)d_in[1];
    const float* sd = (const float*)d_in[2];
    const float* p  = (const float*)d_in[3];

    float* out      = (float*)d_out;
    float* out_m    = out;
    float* out_sd   = out + (size_t)NN * KD;
    float* out_p    = out + 2 * (size_t)NN * KD;
    float* out_asgn = out_p + NN;

    cudaFuncSetAttribute(k_gemm, cudaFuncAttributeMaxDynamicSharedMemorySize, SM_TOTAL);

    const int conv_blocks = (int)(((size_t)BB * KD + (size_t)NN * KD) / 8 / 256);
    k_quant<<<conv_blocks, 256>>>(y, m);
    dim3 grid(NN / 128, BB / 128, KSPL);
    k_gemm<<<grid, 256, SM_TOTAL>>>();
    k_argmin_rescore<<<BB, 128>>>(y, m, out_asgn);
    k_group<<<NN, 32>>>(p, out_p);
    dim3 ugrid(NN, GCH);
    k_update<<<ugrid, 256>>>(y, m, sd, out_m, out_sd);
}